// round 1
// baseline (speedup 1.0000x reference)
#include <cuda_runtime.h>

#define SEQ   1024
#define BATCH 1024
#define TAG   32
#define START 30   // TAG - 2
#define ENDT  31   // TAG - 1
#define PF    4

struct __align__(16) ull2 { unsigned long long x, y; };

__device__ __forceinline__ unsigned long long pk2(float lo, float hi) {
    unsigned long long r;
    asm("mov.b64 %0, {%1, %2};" : "=l"(r) : "f"(lo), "f"(hi));
    return r;
}
__device__ __forceinline__ void fma2(unsigned long long& d, unsigned long long a, unsigned long long b) {
    asm("fma.rn.f32x2 %0, %1, %2, %0;" : "+l"(d) : "l"(a), "l"(b));
}
__device__ __forceinline__ unsigned long long add2(unsigned long long a, unsigned long long b) {
    unsigned long long r;
    asm("add.rn.f32x2 %0, %1, %2;" : "=l"(r) : "l"(a), "l"(b));
    return r;
}
__device__ __forceinline__ void unpk2(unsigned long long v, float& lo, float& hi) {
    asm("mov.b64 {%0, %1}, %2;" : "=f"(lo), "=f"(hi) : "l"(v));
}

// One warp (= one 32-thread block) per batch element. lane = tag index.
__global__ void __launch_bounds__(32) crf_fwd_kernel(
    const float* __restrict__ feats,   // (SEQ, BATCH, TAG) f32
    const float* __restrict__ mask,    // (SEQ, BATCH) f32, monotone per column
    const float* __restrict__ trans,   // (TAG, TAG) f32
    float* __restrict__ out)           // (BATCH,) f32
{
    const int b    = blockIdx.x;
    const int lane = threadIdx.x;

    // Double-buffered e-exchange array -> only ONE barrier per step.
    __shared__ __align__(16) float e_sh[2][TAG];

    // ---- Precompute expT row `lane`, packed as 16 f32x2 registers. ----
    // Row START is exp(-10000) = 0 everywhere -> s[START] = 0 -> alpha[START] = -inf,
    // which behaves identically to the reference's ~-10000 values (exp underflow to 0).
    unsigned long long rowp[16];
#pragma unroll
    for (int k = 0; k < 16; k++) {
        float t0 = __expf(trans[lane * TAG + 2 * k]);
        float t1 = __expf(trans[lane * TAG + 2 * k + 1]);
        rowp[k] = pk2(t0, t1);
    }
    const float tEnd = trans[ENDT * TAG + lane];

    // ---- Step t=0 analytically: alpha0 is one-hot at START. ----
    // reference: new_alpha[i] = feat0[i] + T[i,START] (other terms underflow),
    // mask[0] == 1 always since lengths >= 512.
    float alpha = feats[b * TAG + lane] + trans[lane * TAG + START];

    // ---- Prefetch feats/mask 4 steps ahead (hide ~577cyc DRAM latency). ----
    float fbuf[PF], mbuf[PF];
#pragma unroll
    for (int k = 0; k < PF; k++) {
        const int t = 1 + k;
        fbuf[k] = feats[t * (BATCH * TAG) + b * TAG + lane];
        mbuf[k] = mask[t * BATCH + b];
    }

#pragma unroll 4
    for (int t = 1; t < SEQ; t++) {
        const int slot = (t - 1) & (PF - 1);
        const float ft = fbuf[slot];
        const float mk = mbuf[slot];
        // mask is monotone per batch: once 0, alpha is frozen forever.
        if (mk == 0.0f) break;

        const int tp = t + PF;
        if (tp < SEQ) {
            fbuf[slot] = feats[tp * (BATCH * TAG) + b * TAG + lane];
            mbuf[slot] = mask[tp * BATCH + b];
        }

        // Stability anchor: lane 0's alpha (always finite for t>=1; tag-spread
        // of alpha is bounded by ~20 << 88, so exp never overflows).
        const float m = __shfl_sync(0xffffffffu, alpha, 0);
        const float e = __expf(alpha - m);   // underflows to exactly 0 for alpha = -inf

        const int buf = t & 1;
        e_sh[buf][lane] = e;
        __syncthreads();   // nw=1 BAR: ~3 cyc. Double-buffer removes the WAR barrier.

        // s_i = sum_j expT[i,j] * e_j : 8x LDS.128 + 16x packed FFMA2, 2 chains.
        unsigned long long acc0 = 0ull, acc1 = 0ull;  // (0.0f, 0.0f) bit pattern
        const ull2* e2 = reinterpret_cast<const ull2*>(e_sh[buf]);
#pragma unroll
        for (int k = 0; k < 8; k++) {
            ull2 ev = e2[k];                 // e[4k..4k+3]
            fma2(acc0, ev.x, rowp[2 * k]);
            fma2(acc1, ev.y, rowp[2 * k + 1]);
        }
        float lo, hi;
        unpk2(add2(acc0, acc1), lo, hi);
        const float s = lo + hi;

        alpha = ft + m + __logf(s);          // log(0) = -inf for the START row: correct
    }

    // ---- Final: out[b] = logsumexp_i(alpha[i] + T[END,i]) ----
    float v  = alpha + tEnd;
    float mx = v;
#pragma unroll
    for (int o = 16; o > 0; o >>= 1)
        mx = fmaxf(mx, __shfl_xor_sync(0xffffffffu, mx, o));
    float ex = __expf(v - mx);               // exp(-inf - mx) = 0: fine
#pragma unroll
    for (int o = 16; o > 0; o >>= 1)
        ex += __shfl_xor_sync(0xffffffffu, ex, o);

    if (lane == 0) out[b] = mx + __logf(ex);
}

extern "C" void kernel_launch(void* const* d_in, const int* in_sizes, int n_in,
                              void* d_out, int out_size)
{
    // Identify inputs by element count (robust to ordering).
    const float* feats = nullptr;
    const float* mask  = nullptr;
    const float* trans = nullptr;
    for (int i = 0; i < n_in; i++) {
        if (in_sizes[i] == SEQ * BATCH * TAG)      feats = (const float*)d_in[i];
        else if (in_sizes[i] == SEQ * BATCH)       mask  = (const float*)d_in[i];
        else if (in_sizes[i] == TAG * TAG)         trans = (const float*)d_in[i];
    }
    crf_fwd_kernel<<<BATCH, 32>>>(feats, mask, trans, (float*)d_out);
}

// round 2
// speedup vs baseline: 1.0207x; 1.0207x over previous
#include <cuda_runtime.h>

#define SEQ   1024
#define BATCH 1024
#define TAG   32
#define START 30   // TAG - 2
#define ENDT  31   // TAG - 1
#define PF    4

struct __align__(16) ull2 { unsigned long long x, y; };

__device__ __forceinline__ unsigned long long pk2(float lo, float hi) {
    unsigned long long r;
    asm("mov.b64 %0, {%1, %2};" : "=l"(r) : "f"(lo), "f"(hi));
    return r;
}
__device__ __forceinline__ void fma2(unsigned long long& d, unsigned long long a, unsigned long long b) {
    asm("fma.rn.f32x2 %0, %1, %2, %0;" : "+l"(d) : "l"(a), "l"(b));
}
__device__ __forceinline__ unsigned long long add2(unsigned long long a, unsigned long long b) {
    unsigned long long r;
    asm("add.rn.f32x2 %0, %1, %2;" : "=l"(r) : "l"(a), "l"(b));
    return r;
}
__device__ __forceinline__ void unpk2(unsigned long long v, float& lo, float& hi) {
    asm("mov.b64 {%0, %1}, %2;" : "=f"(lo), "=f"(hi) : "l"(v));
}

// One warp (= one 32-thread block) per batch element. lane = tag index.
__global__ void __launch_bounds__(32) crf_fwd_kernel(
    const float* __restrict__ feats,   // (SEQ, BATCH, TAG) f32
    const float* __restrict__ mask,    // (SEQ, BATCH) f32, monotone per column
    const float* __restrict__ trans,   // (TAG, TAG) f32
    float* __restrict__ out)           // (BATCH,) f32
{
    const int b    = blockIdx.x;
    const int lane = threadIdx.x;

    // Double-buffered e-exchange array -> only ONE barrier per step.
    __shared__ __align__(16) float e_sh[2][TAG];

    // ---- Precompute expT row `lane`, packed as 16 f32x2 registers. ----
    // Row START is exp(-10000) = 0 everywhere -> s[START] = 0 -> alpha[START] = -inf,
    // which behaves identically to the reference's ~-10000 values (exp underflow to 0).
    unsigned long long rowp[16];
#pragma unroll
    for (int k = 0; k < 16; k++) {
        float t0 = __expf(trans[lane * TAG + 2 * k]);
        float t1 = __expf(trans[lane * TAG + 2 * k + 1]);
        rowp[k] = pk2(t0, t1);
    }
    const float tEnd = trans[ENDT * TAG + lane];

    // ---- Step t=0 analytically: alpha0 is one-hot at START. ----
    // reference: new_alpha[i] = feat0[i] + T[i,START] (other terms underflow),
    // mask[0] == 1 always since lengths >= 512.
    float alpha = feats[b * TAG + lane] + trans[lane * TAG + START];

    // ---- Prefetch feats/mask 4 steps ahead (hide ~577cyc DRAM latency). ----
    float fbuf[PF], mbuf[PF];
#pragma unroll
    for (int k = 0; k < PF; k++) {
        const int t = 1 + k;
        fbuf[k] = feats[t * (BATCH * TAG) + b * TAG + lane];
        mbuf[k] = mask[t * BATCH + b];
    }

#pragma unroll 4
    for (int t = 1; t < SEQ; t++) {
        const int slot = (t - 1) & (PF - 1);
        const float ft = fbuf[slot];
        const float mk = mbuf[slot];
        // mask is monotone per batch: once 0, alpha is frozen forever.
        if (mk == 0.0f) break;

        const int tp = t + PF;
        if (tp < SEQ) {
            fbuf[slot] = feats[tp * (BATCH * TAG) + b * TAG + lane];
            mbuf[slot] = mask[tp * BATCH + b];
        }

        // Stability anchor: lane 0's alpha (always finite for t>=1; tag-spread
        // of alpha is bounded by ~20 << 88, so exp never overflows).
        const float m = __shfl_sync(0xffffffffu, alpha, 0);
        const float e = __expf(alpha - m);   // underflows to exactly 0 for alpha = -inf

        const int buf = t & 1;
        e_sh[buf][lane] = e;
        __syncthreads();   // nw=1 BAR: ~3 cyc. Double-buffer removes the WAR barrier.

        // s_i = sum_j expT[i,j] * e_j : 8x LDS.128 + 16x packed FFMA2, 2 chains.
        unsigned long long acc0 = 0ull, acc1 = 0ull;  // (0.0f, 0.0f) bit pattern
        const ull2* e2 = reinterpret_cast<const ull2*>(e_sh[buf]);
#pragma unroll
        for (int k = 0; k < 8; k++) {
            ull2 ev = e2[k];                 // e[4k..4k+3]
            fma2(acc0, ev.x, rowp[2 * k]);
            fma2(acc1, ev.y, rowp[2 * k + 1]);
        }
        float lo, hi;
        unpk2(add2(acc0, acc1), lo, hi);
        const float s = lo + hi;

        alpha = ft + m + __logf(s);          // log(0) = -inf for the START row: correct
    }

    // ---- Final: out[b] = logsumexp_i(alpha[i] + T[END,i]) ----
    float v  = alpha + tEnd;
    float mx = v;
#pragma unroll
    for (int o = 16; o > 0; o >>= 1)
        mx = fmaxf(mx, __shfl_xor_sync(0xffffffffu, mx, o));
    float ex = __expf(v - mx);               // exp(-inf - mx) = 0: fine
#pragma unroll
    for (int o = 16; o > 0; o >>= 1)
        ex += __shfl_xor_sync(0xffffffffu, ex, o);

    if (lane == 0) out[b] = mx + __logf(ex);
}

extern "C" void kernel_launch(void* const* d_in, const int* in_sizes, int n_in,
                              void* d_out, int out_size)
{
    // Identify inputs by element count (robust to ordering).
    const float* feats = nullptr;
    const float* mask  = nullptr;
    const float* trans = nullptr;
    for (int i = 0; i < n_in; i++) {
        if (in_sizes[i] == SEQ * BATCH * TAG)      feats = (const float*)d_in[i];
        else if (in_sizes[i] == SEQ * BATCH)       mask  = (const float*)d_in[i];
        else if (in_sizes[i] == TAG * TAG)         trans = (const float*)d_in[i];
    }
    crf_fwd_kernel<<<BATCH, 32>>>(feats, mask, trans, (float*)d_out);
}

// round 3
// speedup vs baseline: 1.5294x; 1.4984x over previous
#include <cuda_runtime.h>

#define SEQ   1024
#define BATCH 1024
#define TAG   32
#define START 30   // TAG - 2
#define ENDT  31   // TAG - 1
#define PF    8    // prefetch depth: 8 * ~85cyc > 577cyc DRAM latency
#define FULL  0xffffffffu

struct __align__(16) ull2 { unsigned long long x, y; };

__device__ __forceinline__ unsigned long long pk2(float lo, float hi) {
    unsigned long long r;
    asm("mov.b64 %0, {%1, %2};" : "=l"(r) : "f"(lo), "f"(hi));
    return r;
}
__device__ __forceinline__ void fma2(unsigned long long& d, unsigned long long a, unsigned long long b) {
    asm("fma.rn.f32x2 %0, %1, %2, %0;" : "+l"(d) : "l"(a), "l"(b));
}
__device__ __forceinline__ unsigned long long add2(unsigned long long a, unsigned long long b) {
    unsigned long long r;
    asm("add.rn.f32x2 %0, %1, %2;" : "=l"(r) : "l"(a), "l"(b));
    return r;
}
__device__ __forceinline__ void unpk2(unsigned long long v, float& lo, float& hi) {
    asm("mov.b64 {%0, %1}, %2;" : "=f"(lo), "=f"(hi) : "l"(v));
}

// Core matvec: s_i = sum_j expT[i,j] * p_j from shared, 4 independent FFMA2 chains.
__device__ __forceinline__ float matvec32(const float* __restrict__ psh,
                                          const unsigned long long* __restrict__ rowp)
{
    const ull2* e2 = reinterpret_cast<const ull2*>(psh);
    unsigned long long acc0 = 0ull, acc1 = 0ull, acc2 = 0ull, acc3 = 0ull;
#pragma unroll
    for (int k = 0; k < 8; k += 2) {
        ull2 evA = e2[k];
        ull2 evB = e2[k + 1];
        fma2(acc0, evA.x, rowp[2 * k]);
        fma2(acc1, evA.y, rowp[2 * k + 1]);
        fma2(acc2, evB.x, rowp[2 * k + 2]);
        fma2(acc3, evB.y, rowp[2 * k + 3]);
    }
    unsigned long long s01 = add2(acc0, acc1);
    unsigned long long s23 = add2(acc2, acc3);
    float lo, hi;
    unpk2(add2(s01, s23), lo, hi);
    return lo + hi;
}

// One warp (= one 32-thread block) per batch element. lane = tag index.
// Linear-domain recurrence: p_i <- exp(ft_i) * sum_j expT[i,j] * p_j,
// uniform log-offset C accumulated off the critical path; renorm every 4 steps,
// with the 1/p0 factor folded into the NEXT step's scale so shfl+rcp overlap
// the matvec instead of extending the chain.
__global__ void __launch_bounds__(32) crf_fwd_kernel(
    const float* __restrict__ feats,   // (SEQ, BATCH, TAG) f32
    const float* __restrict__ mask,    // (SEQ, BATCH) f32, monotone per column
    const float* __restrict__ trans,   // (TAG, TAG) f32
    float* __restrict__ out)           // (BATCH,) f32
{
    const int b    = blockIdx.x;
    const int lane = threadIdx.x;

    // Double-buffered exchange: one BAR per step (write buf, BAR, read buf).
    __shared__ __align__(16) float p_sh[2][TAG];

    // ---- expT row `lane`, packed as 16 f32x2 registers. Row START = all zeros. ----
    unsigned long long rowp[16];
#pragma unroll
    for (int k = 0; k < 16; k++) {
        float t0 = __expf(trans[lane * TAG + 2 * k]);
        float t1 = __expf(trans[lane * TAG + 2 * k + 1]);
        rowp[k] = pk2(t0, t1);
    }
    const float tEnd = trans[ENDT * TAG + lane];

    // ---- Trip count L = sum of (monotone) mask column; removes in-loop mask+break. ----
    float msum = 0.0f;
#pragma unroll
    for (int k = 0; k < SEQ / TAG; k++)
        msum += mask[(k * TAG + lane) * BATCH + b];
#pragma unroll
    for (int o = 16; o > 0; o >>= 1)
        msum += __shfl_xor_sync(FULL, msum, o);
    const int L = (int)(msum + 0.5f);   // exact: mask is 0/1, L <= 1024

    // ---- Step t=0 analytically: alpha0 one-hot at START. ----
    const float a0 = feats[b * TAG + lane] + trans[lane * TAG + START];
    float C = __shfl_sync(FULL, a0, 0);       // uniform anchor
    float p = __expf(a0 - C);                 // p[START] underflows to exactly 0

    // ---- Prefetch ring of exp(feat): MUFU happens at load time, off the chain. ----
    float efb[PF];
#pragma unroll
    for (int k = 0; k < PF; k++) {
        const int tc = min(1 + k, SEQ - 1);
        efb[k] = __expf(feats[tc * (BATCH * TAG) + b * TAG + lane]);
    }

    int t = 1;
    const int ngroups = (L - 1) >> 2;
    for (int g = 0; g < ngroups; g++) {
        // Renorm scalars for this group; shfl/rcp/log overlap step s=0's matvec.
        const float p0 = __shfl_sync(FULL, p, 0);   // > 0 always (tag 0 is a live tag)
        const float rn = __fdividef(1.0f, p0);
        C += __logf(p0);
#pragma unroll
        for (int s = 0; s < 4; s++) {
            const int tt  = t + s;
            const int buf = tt & 1;
            p_sh[buf][lane] = p;
            __syncthreads();                        // nw=1 BAR, also drains STS
            const float sval = matvec32(p_sh[buf], rowp);
            float scale = efb[(tt - 1) & (PF - 1)];
            if (s == 0) scale *= rn;                // s compile-time: no branch
            p = sval * scale;
            // Prefetch exp(feat) 8 steps ahead (clamped address, branch-free).
            const int tpc = min(tt + PF, SEQ - 1);
            efb[(tt - 1) & (PF - 1)] =
                __expf(feats[tpc * (BATCH * TAG) + b * TAG + lane]);
        }
        t += 4;
    }
    // Remainder (<= 3 steps, no renorm needed: range headroom analyzed safe).
    for (; t < L; t++) {
        const int buf = t & 1;
        p_sh[buf][lane] = p;
        __syncthreads();
        const float sval = matvec32(p_sh[buf], rowp);
        p = sval * efb[(t - 1) & (PF - 1)];
    }

    // ---- Final: out[b] = logsumexp_i(log p_i + C + T[END,i]) ----
    const float v = __logf(p) + C + tEnd;   // log(0) = -inf for dead tags: fine
    float mx = v;
#pragma unroll
    for (int o = 16; o > 0; o >>= 1)
        mx = fmaxf(mx, __shfl_xor_sync(FULL, mx, o));
    float ex = __expf(v - mx);              // exp(-inf - mx) = 0
#pragma unroll
    for (int o = 16; o > 0; o >>= 1)
        ex += __shfl_xor_sync(FULL, ex, o);

    if (lane == 0) out[b] = mx + __logf(ex);
}

extern "C" void kernel_launch(void* const* d_in, const int* in_sizes, int n_in,
                              void* d_out, int out_size)
{
    const float* feats = nullptr;
    const float* mask  = nullptr;
    const float* trans = nullptr;
    for (int i = 0; i < n_in; i++) {
        if (in_sizes[i] == SEQ * BATCH * TAG)      feats = (const float*)d_in[i];
        else if (in_sizes[i] == SEQ * BATCH)       mask  = (const float*)d_in[i];
        else if (in_sizes[i] == TAG * TAG)         trans = (const float*)d_in[i];
    }
    crf_fwd_kernel<<<BATCH, 32>>>(feats, mask, trans, (float*)d_out);
}